// round 2
// baseline (speedup 1.0000x reference)
#include <cuda_runtime.h>

// Problem shape (fixed by the dataset): N=10000 nodes, E=320000 edges,
// node_dim = out_dim = 128, init_dim = 257.
#define DIM 128
#define MAX_N 10016
#define MAX_E 320064

// Scratch (static __device__ — no allocation allowed)
__device__ float g_P1[MAX_N * DIM];     // atom @ (W1a+W2)^T
__device__ float g_P2[MAX_N * DIM];     // atom @ (W1b+W2)^T
__device__ float g_At[DIM * DIM];       // transposed combined weight A: At[k*128+o]
__device__ float g_Bt[DIM * DIM];       // transposed combined weight B
__device__ float g_wc[DIM];             // W1[:,256]  (bond column)
__device__ float g_bias[DIM];           // b1 + b2

// ---------------------------------------------------------------------------
// Kernel 0: combine + transpose weights.  grid=(128), block=(128).
// W1 is [128, 257] row-major; W2 is [128, 128] row-major.
// ---------------------------------------------------------------------------
__global__ void prep_weights(const float* __restrict__ W1,
                             const float* __restrict__ b1,
                             const float* __restrict__ W2,
                             const float* __restrict__ b2) {
    const int k = blockIdx.x;    // 0..127 (input feature index)
    const int o = threadIdx.x;   // 0..127 (output index)
    const float w2 = W2[o * DIM + k];
    g_At[k * DIM + o] = W1[o * 257 + k]       + w2;
    g_Bt[k * DIM + o] = W1[o * 257 + DIM + k] + w2;
    if (k == 0) {
        g_wc[o]   = W1[o * 257 + 256];
        g_bias[o] = b1[o] + b2[o];
    }
}

// ---------------------------------------------------------------------------
// Kernel 1: node projections.  8 nodes per block, 128 threads.
// Each thread owns one output column o; loops over k with the atom rows in
// shared memory (broadcast reads) and coalesced loads of At/Bt.
// ---------------------------------------------------------------------------
#define NPB 8
__global__ void node_proj(const float* __restrict__ atom, int N) {
    __shared__ float sA[NPB][DIM];
    const int base = blockIdx.x * NPB;
    const int t = threadIdx.x;

    #pragma unroll
    for (int i = 0; i < NPB; i++) {
        int n = base + i;
        sA[i][t] = (n < N) ? atom[n * DIM + t] : 0.0f;
    }
    __syncthreads();

    float acc1[NPB], acc2[NPB];
    #pragma unroll
    for (int i = 0; i < NPB; i++) { acc1[i] = 0.0f; acc2[i] = 0.0f; }

    const int o = t;
    #pragma unroll 4
    for (int k = 0; k < DIM; k++) {
        const float a = g_At[k * DIM + o];
        const float b = g_Bt[k * DIM + o];
        #pragma unroll
        for (int i = 0; i < NPB; i++) {
            acc1[i] = fmaf(sA[i][k], a, acc1[i]);
            acc2[i] = fmaf(sA[i][k], b, acc2[i]);
        }
    }

    #pragma unroll
    for (int i = 0; i < NPB; i++) {
        int n = base + i;
        if (n < N) {
            g_P1[n * DIM + o] = acc1[i];
            g_P2[n * DIM + o] = acc2[i];
        }
    }
}

// ---------------------------------------------------------------------------
// Kernel 2: edge gather + add + leaky_relu.
// One warp per edge-slice; each lane handles one float4 (4 output columns).
// EPW edges per warp to amortize the wc/bias register loads.
// ---------------------------------------------------------------------------
#define EPW 4
#define NEG_SLOPE 0.01f

__device__ __forceinline__ float lrelu(float x) {
    return x > 0.0f ? x : NEG_SLOPE * x;
}

__global__ void edge_kernel(const float* __restrict__ bond,
                            const int* __restrict__ src,
                            const int* __restrict__ dst,
                            float* __restrict__ out, int E) {
    const int lane = threadIdx.x & 31;
    const int warp = threadIdx.x >> 5;
    const int wpb  = blockDim.x >> 5;

    const float4 wc4 = reinterpret_cast<const float4*>(g_wc)[lane];
    const float4 bs4 = reinterpret_cast<const float4*>(g_bias)[lane];

    const float4* __restrict__ P1 = reinterpret_cast<const float4*>(g_P1);
    const float4* __restrict__ P2 = reinterpret_cast<const float4*>(g_P2);
    float4* __restrict__ O = reinterpret_cast<float4*>(out);

    const int e0 = (blockIdx.x * wpb + warp) * EPW;

    #pragma unroll
    for (int i = 0; i < EPW; i++) {
        const int e = e0 + i;
        if (e >= E) return;
        const int s = __ldg(src + e);
        const int d = __ldg(dst + e);
        const float bw = __ldg(bond + e);

        const float4 p = P1[s * (DIM / 4) + lane];
        const float4 q = P2[d * (DIM / 4) + lane];

        float4 r;
        r.x = lrelu(p.x + q.x + fmaf(bw, wc4.x, bs4.x));
        r.y = lrelu(p.y + q.y + fmaf(bw, wc4.y, bs4.y));
        r.z = lrelu(p.z + q.z + fmaf(bw, wc4.z, bs4.z));
        r.w = lrelu(p.w + q.w + fmaf(bw, wc4.w, bs4.w));

        O[e * (DIM / 4) + lane] = r;
    }
}

// ---------------------------------------------------------------------------
// Launcher.  Inputs (metadata order):
//   0: atom_feats [N,128] f32   1: bond_feats [E,1] f32
//   2: src [E] i32              3: dst [E] i32
//   4: W1 [128,257] f32         5: b1 [128] f32
//   6: W2 [128,128] f32         7: b2 [128] f32
// Output: [E,128] f32
// ---------------------------------------------------------------------------
extern "C" void kernel_launch(void* const* d_in, const int* in_sizes, int n_in,
                              void* d_out, int out_size) {
    const float* atom = (const float*)d_in[0];
    const float* bond = (const float*)d_in[1];
    const int*   src  = (const int*)d_in[2];
    const int*   dst  = (const int*)d_in[3];
    const float* W1   = (const float*)d_in[4];
    const float* b1   = (const float*)d_in[5];
    const float* W2   = (const float*)d_in[6];
    const float* b2   = (const float*)d_in[7];
    float* out = (float*)d_out;

    const int N = in_sizes[0] / DIM;
    const int E = in_sizes[2];

    prep_weights<<<DIM, DIM>>>(W1, b1, W2, b2);

    node_proj<<<(N + NPB - 1) / NPB, DIM>>>(atom, N);

    const int threads = 256;                    // 8 warps/block
    const int edges_per_block = (threads / 32) * EPW;   // 32
    edge_kernel<<<(E + edges_per_block - 1) / edges_per_block, threads>>>(
        bond, src, dst, out, E);
}

// round 3
// speedup vs baseline: 1.8726x; 1.8726x over previous
#include <cuda_runtime.h>
#include <cuda_fp16.h>

// Fixed shapes: N=10000 nodes, E=320000 edges, node_dim=out_dim=128, init_dim=257.
#define DIM 128
#define MAX_N 10016
#define MAX_E 320064
#define NEG_SLOPE 0.01f

// Static scratch (no allocation allowed)
__device__ __half g_P1h[MAX_N * DIM];   // fp16: atom @ (W1a+W2)^T
__device__ __half g_P2h[MAX_N * DIM];   // fp16: atom @ (W1b+W2)^T
__device__ float  g_At[DIM * DIM];      // combined weight A, transposed: At[k*128+o]
__device__ float  g_Bt[DIM * DIM];      // combined weight B, transposed
__device__ float  g_wc[DIM];            // W1[:,256]
__device__ float  g_bias[DIM];          // b1 + b2

// ---- f32x2 packed-FMA helpers (Blackwell PTX) -----------------------------
__device__ __forceinline__ unsigned long long pack2(float x, float y) {
    unsigned long long r;
    asm("mov.b64 %0, {%1, %2};" : "=l"(r) : "f"(x), "f"(y));
    return r;
}
__device__ __forceinline__ void unpack2(unsigned long long v, float& x, float& y) {
    asm("mov.b64 {%0, %1}, %2;" : "=f"(x), "=f"(y) : "l"(v));
}
__device__ __forceinline__ void ffma2(unsigned long long& d,
                                      unsigned long long a, unsigned long long b) {
    asm("fma.rn.f32x2 %0, %1, %2, %0;" : "+l"(d) : "l"(a), "l"(b));
}

// ---------------------------------------------------------------------------
// Kernel 0: combine + transpose weights. blockIdx = o (output), threadIdx = k.
// W1 [128,257] row-major, W2 [128,128] row-major. Loads coalesced; scattered
// stores are fire-and-forget (tiny volume).
// ---------------------------------------------------------------------------
__global__ void prep_weights(const float* __restrict__ W1,
                             const float* __restrict__ b1,
                             const float* __restrict__ W2,
                             const float* __restrict__ b2) {
    const int o = blockIdx.x;    // 0..127
    const int k = threadIdx.x;   // 0..127
    const float w2 = W2[o * DIM + k];
    g_At[k * DIM + o] = W1[o * 257 + k]       + w2;
    g_Bt[k * DIM + o] = W1[o * 257 + DIM + k] + w2;
    if (k == 0) {
        g_wc[o]   = W1[o * 257 + 256];
        g_bias[o] = b1[o] + b2[o];
    }
}

// ---------------------------------------------------------------------------
// Kernel 1: node projections with packed f32x2 FMA.
// 16 nodes per block (8 node-pairs), 128 threads; thread t owns output o=t.
// Node pairs pre-packed as float2 in smem -> inner loop is LDS.64 broadcast
// + 2x ffma2 per pair per weight-table.
// ---------------------------------------------------------------------------
#define NPB   16
#define NPAIR (NPB / 2)
__global__ void __launch_bounds__(128) node_proj(const float* __restrict__ atom, int N) {
    __shared__ float2 sPair[NPAIR][DIM];   // sPair[j][k] = (atom[2j][k], atom[2j+1][k])
    const int base = blockIdx.x * NPB;
    const int t = threadIdx.x;             // 0..127 = output column o

    // Fill packed node-pairs (coalesced loads, conflict-free 8B stores)
    #pragma unroll
    for (int j = 0; j < NPAIR; j++) {
        int n0 = base + 2 * j, n1 = n0 + 1;
        float v0 = (n0 < N) ? atom[n0 * DIM + t] : 0.0f;
        float v1 = (n1 < N) ? atom[n1 * DIM + t] : 0.0f;
        sPair[j][t] = make_float2(v0, v1);
    }
    __syncthreads();

    unsigned long long acc1[NPAIR], acc2[NPAIR];
    #pragma unroll
    for (int j = 0; j < NPAIR; j++) { acc1[j] = 0ull; acc2[j] = 0ull; }

    const int o = t;
    #pragma unroll 4
    for (int k = 0; k < DIM; k++) {
        const float a = g_At[k * DIM + o];    // coalesced, L1/L2 resident
        const float b = g_Bt[k * DIM + o];
        const unsigned long long aa = pack2(a, a);
        const unsigned long long bb = pack2(b, b);
        #pragma unroll
        for (int j = 0; j < NPAIR; j++) {
            const unsigned long long vv =
                *reinterpret_cast<const unsigned long long*>(&sPair[j][k]);  // broadcast
            ffma2(acc1[j], vv, aa);
            ffma2(acc2[j], vv, bb);
        }
    }

    #pragma unroll
    for (int j = 0; j < NPAIR; j++) {
        int n0 = base + 2 * j, n1 = n0 + 1;
        float p0, p1, q0, q1;
        unpack2(acc1[j], p0, p1);
        unpack2(acc2[j], q0, q1);
        if (n0 < N) { g_P1h[n0 * DIM + o] = __float2half_rn(p0);
                      g_P2h[n0 * DIM + o] = __float2half_rn(q0); }
        if (n1 < N) { g_P1h[n1 * DIM + o] = __float2half_rn(p1);
                      g_P2h[n1 * DIM + o] = __float2half_rn(q1); }
    }
}

// ---------------------------------------------------------------------------
// Kernel 2: edge gather (fp16) + add + leaky_relu, f32 output via streaming
// stores. One warp per edge group; lane covers 4 output columns (8B gather
// per lane -> 256B per row gather, fully coalesced).
// ---------------------------------------------------------------------------
#define EPW 4
__device__ __forceinline__ float lrelu(float x) {
    return x > 0.0f ? x : NEG_SLOPE * x;
}

__global__ void __launch_bounds__(256) edge_kernel(const float* __restrict__ bond,
                            const int* __restrict__ src,
                            const int* __restrict__ dst,
                            float* __restrict__ out, int E) {
    const int lane = threadIdx.x & 31;
    const int warp = threadIdx.x >> 5;
    const int wpb  = blockDim.x >> 5;

    const float4 wc4 = reinterpret_cast<const float4*>(g_wc)[lane];
    const float4 bs4 = reinterpret_cast<const float4*>(g_bias)[lane];

    const uint2* __restrict__ P1 = reinterpret_cast<const uint2*>(g_P1h);
    const uint2* __restrict__ P2 = reinterpret_cast<const uint2*>(g_P2h);
    float4* __restrict__ O = reinterpret_cast<float4*>(out);

    const int e0 = (blockIdx.x * wpb + warp) * EPW;

    #pragma unroll
    for (int i = 0; i < EPW; i++) {
        const int e = e0 + i;
        if (e >= E) return;
        const int s = __ldg(src + e);
        const int d = __ldg(dst + e);
        const float bw = __ldg(bond + e);

        uint2 pu = __ldg(&P1[s * (DIM / 4) + lane]);
        uint2 qu = __ldg(&P2[d * (DIM / 4) + lane]);
        const float2 pa = __half22float2(*reinterpret_cast<__half2*>(&pu.x));
        const float2 pb = __half22float2(*reinterpret_cast<__half2*>(&pu.y));
        const float2 qa = __half22float2(*reinterpret_cast<__half2*>(&qu.x));
        const float2 qb = __half22float2(*reinterpret_cast<__half2*>(&qu.y));

        float4 r;
        r.x = lrelu(pa.x + qa.x + fmaf(bw, wc4.x, bs4.x));
        r.y = lrelu(pa.y + qa.y + fmaf(bw, wc4.y, bs4.y));
        r.z = lrelu(pb.x + qb.x + fmaf(bw, wc4.z, bs4.z));
        r.w = lrelu(pb.y + qb.y + fmaf(bw, wc4.w, bs4.w));

        __stcs(&O[e * (DIM / 4) + lane], r);   // streaming: don't evict P tables
    }
}

// ---------------------------------------------------------------------------
// Launcher. Inputs: 0 atom[N,128] 1 bond[E,1] 2 src[E] 3 dst[E]
//                   4 W1[128,257] 5 b1[128] 6 W2[128,128] 7 b2[128]
// Output: [E,128] f32
// ---------------------------------------------------------------------------
extern "C" void kernel_launch(void* const* d_in, const int* in_sizes, int n_in,
                              void* d_out, int out_size) {
    const float* atom = (const float*)d_in[0];
    const float* bond = (const float*)d_in[1];
    const int*   src  = (const int*)d_in[2];
    const int*   dst  = (const int*)d_in[3];
    const float* W1   = (const float*)d_in[4];
    const float* b1   = (const float*)d_in[5];
    const float* W2   = (const float*)d_in[6];
    const float* b2   = (const float*)d_in[7];
    float* out = (float*)d_out;

    const int N = in_sizes[0] / DIM;
    const int E = in_sizes[2];

    prep_weights<<<DIM, DIM>>>(W1, b1, W2, b2);
    node_proj<<<(N + NPB - 1) / NPB, DIM>>>(atom, N);

    const int threads = 256;                          // 8 warps/block
    const int edges_per_block = (threads / 32) * EPW; // 32
    edge_kernel<<<(E + edges_per_block - 1) / edges_per_block, threads>>>(
        bond, src, dst, out, E);
}